// round 7
// baseline (speedup 1.0000x reference)
#include <cuda_runtime.h>
#include <cuda_bf16.h>
#include <cstdint>

// Problem constants: B=512, conv in [512,128,1024], k=5 VALID -> L=1020
// LSTM1 H=32 (in 128), LSTM2 H=16 (in 32), LSTM3 H=32 (in 16). Out: [512,32].
#define BATCH 512
#define TSEQ  1020
#define MROWS (BATCH * TSEQ)   // 522240

// ---------------------------------------------------------------------------
// Device scratch (no runtime allocation allowed). ~1.04 GB total.
// ---------------------------------------------------------------------------
__device__ __align__(256) float g_conv[66846720];  // [B][128][1020] flat == A1 [M][128]
__device__ __align__(256) float g_xg1 [66846720];  // [M][128] gate-permuted
__device__ __align__(256) float g_h1  [16711680];  // [M][32]
__device__ __align__(256) float g_xg2 [33423360];  // [M][64] gate-permuted
__device__ __align__(256) float g_h2  [ 8355840];  // [M][16]
__device__ __align__(256) float g_xg3 [66846720];  // [M][128] gate-permuted
__device__ __align__(256) float g_w1p [16384];     // [128][128] permuted Wih1
__device__ __align__(256) float g_b1p [128];
__device__ __align__(256) float g_w2p [2048];      // [64][32]
__device__ __align__(256) float g_b2p [64];
__device__ __align__(256) float g_w3p [2048];      // [128][16]
__device__ __align__(256) float g_b3p [128];

__device__ __forceinline__ float sigf(float x) {
    return __fdividef(1.0f, 1.0f + __expf(-x));
}
__device__ __forceinline__ float tanha(float x) {
    // tanh(x) = 2*sigmoid(2x) - 1 ; correct saturation for large |x|
    return 2.0f * __fdividef(1.0f, 1.0f + __expf(-2.0f * x)) - 1.0f;
}

// ---------------------------------------------------------------------------
// Gate permutation: Wp[p][k] with p = l*4 + j  (j in {i,f,g,o}), source row j*H+l.
// Also folds bih+bhh into bp[p].
// ---------------------------------------------------------------------------
__global__ void k_perm(const float* __restrict__ Wih, const float* __restrict__ bih,
                       const float* __restrict__ bhh, float* __restrict__ Wp,
                       float* __restrict__ bp, int H, int K) {
    int idx = blockIdx.x * 256 + threadIdx.x;
    int N = 4 * H;
    if (idx < N * K) {
        int p = idx / K, k = idx % K;
        int j = p & 3, l = p >> 2;
        Wp[idx] = Wih[(j * H + l) * K + k];
    }
    if (idx < N) {
        int j = idx & 3, l = idx >> 2;
        bp[idx] = bih[j * H + l] + bhh[j * H + l];
    }
}

// ---------------------------------------------------------------------------
// conv1d VALID k=5: out[b][oc][l] = cb[oc] + sum_{ic,k} x[b][ic][l+k]*w[oc][ic][k]
// Tile: 64 oc x 64 l per block, thread tile 4x4, ic chunks of 8 in smem.
// ---------------------------------------------------------------------------
__global__ __launch_bounds__(256) void k_conv(const float* __restrict__ x,
                                              const float* __restrict__ w,
                                              const float* __restrict__ cb,
                                              float* __restrict__ out) {
    __shared__ float xs[8][68];
    __shared__ float ws[64][40];
    const int t  = threadIdx.x;
    const int tx = t & 15;        // 16 l-thread groups (4 l each)
    const int ty = t >> 4;        // 16 oc-thread groups (4 oc each)
    const int l0  = blockIdx.x * 64;
    const int oc0 = blockIdx.y * 64;
    const int b   = blockIdx.z;
    const float* xb = x + (size_t)b * 131072;   // 128*1024

    float acc[4][4];
#pragma unroll
    for (int o = 0; o < 4; o++)
#pragma unroll
        for (int j = 0; j < 4; j++) acc[o][j] = 0.f;

    for (int ic0 = 0; ic0 < 128; ic0 += 8) {
        for (int idx = t; idx < 8 * 68; idx += 256) {
            int ic = idx / 68, col = idx % 68;
            int gcol = l0 + col;
            xs[ic][col] = (gcol < 1024) ? xb[(ic0 + ic) * 1024 + gcol] : 0.f;
        }
        for (int idx = t; idx < 64 * 40; idx += 256) {
            int oc = idx / 40, rem = idx % 40;
            ws[oc][rem] = w[(oc0 + oc) * 640 + ic0 * 5 + rem];
        }
        __syncthreads();
#pragma unroll
        for (int ic = 0; ic < 8; ic++) {
#pragma unroll
            for (int k = 0; k < 5; k++) {
                float xv[4], wv[4];
#pragma unroll
                for (int j = 0; j < 4; j++) xv[j] = xs[ic][tx * 4 + j + k];
#pragma unroll
                for (int o = 0; o < 4; o++) wv[o] = ws[ty * 4 + o][ic * 5 + k];
#pragma unroll
                for (int o = 0; o < 4; o++)
#pragma unroll
                    for (int j = 0; j < 4; j++) acc[o][j] += wv[o] * xv[j];
            }
        }
        __syncthreads();
    }
#pragma unroll
    for (int o = 0; o < 4; o++) {
        int oc = oc0 + ty * 4 + o;
        float bias = cb[oc];
#pragma unroll
        for (int j = 0; j < 4; j++) {
            int l = l0 + tx * 4 + j;
            if (l < TSEQ)
                out[(size_t)b * 130560 + (size_t)oc * TSEQ + l] = acc[o][j] + bias;
        }
    }
}

// ---------------------------------------------------------------------------
// Xg[m][p] = bp[p] + sum_k A[m][k] * Wp[p*K+k]   (A row-major [M][K])
// Tile: 64 rows x N cols, 256 threads. N in {128,64}, K in {128,32,16}.
// ---------------------------------------------------------------------------
template <int N, int K>
__global__ __launch_bounds__(256) void k_gemm(const float* __restrict__ A,
                                              const float* __restrict__ Wp,
                                              const float* __restrict__ bp,
                                              float* __restrict__ Xg) {
    constexpr int KC  = 16;
    constexpr int CG  = N / 4;      // col-thread count (each 4 cols)
    constexpr int RG  = 256 / CG;   // row-thread groups
    constexpr int RPT = 64 / RG;    // rows per thread
    __shared__ float As[64][KC];
    __shared__ float Ws[KC][N];

    const int t  = threadIdx.x;
    const int cg = t % CG;
    const int rg = t / CG;
    const size_t m0 = (size_t)blockIdx.x * 64;

    float acc[RPT][4];
#pragma unroll
    for (int r = 0; r < RPT; r++)
#pragma unroll
        for (int j = 0; j < 4; j++) acc[r][j] = 0.f;

    for (int kc = 0; kc < K; kc += KC) {
        {   // A tile: 64x16 floats = 256 float4, one per thread (coalesced)
            int row = t >> 2;
            int k4  = (t & 3) * 4;
            float4 v = *(const float4*)&A[(m0 + row) * K + kc + k4];
            *(float4*)&As[row][k4] = v;
        }
#pragma unroll
        for (int e = 0; e < N * KC / 256; e++) {   // W tile, transposed into smem
            int idx = t + e * 256;
            int p = idx % N;
            int kk = idx / N;
            Ws[kk][p] = Wp[p * K + kc + kk];
        }
        __syncthreads();
#pragma unroll
        for (int kk = 0; kk < KC; kk++) {
            float4 w4 = *(const float4*)&Ws[kk][cg * 4];
#pragma unroll
            for (int r = 0; r < RPT; r++) {
                float av = As[rg * RPT + r][kk];
                acc[r][0] += av * w4.x;
                acc[r][1] += av * w4.y;
                acc[r][2] += av * w4.z;
                acc[r][3] += av * w4.w;
            }
        }
        __syncthreads();
    }
    float4 bv = *(const float4*)&bp[cg * 4];
#pragma unroll
    for (int r = 0; r < RPT; r++) {
        size_t m = m0 + rg * RPT + r;
        float4 o;
        o.x = acc[r][0] + bv.x;
        o.y = acc[r][1] + bv.y;
        o.z = acc[r][2] + bv.z;
        o.w = acc[r][3] + bv.w;
        *(float4*)&Xg[m * N + cg * 4] = o;
    }
}

// ---------------------------------------------------------------------------
// LSTM scan, H=32: one warp per batch, lane = hidden unit. Whh in registers,
// h broadcast via shfl, split accumulators (2x16) to shorten FMA chains.
// hout != nullptr -> store all steps; lastout != nullptr -> store final h.
// ---------------------------------------------------------------------------
__global__ __launch_bounds__(32) void k_scan32(const float* __restrict__ xg,
                                               const float* __restrict__ whh,
                                               float* __restrict__ hout,
                                               float* __restrict__ lastout) {
    const int b = blockIdx.x;
    const int l = threadIdx.x;
    float wi[32], wf[32], wg[32], wo[32];
#pragma unroll
    for (int k = 0; k < 32; k++) {
        wi[k] = whh[(0 * 32 + l) * 32 + k];
        wf[k] = whh[(1 * 32 + l) * 32 + k];
        wg[k] = whh[(2 * 32 + l) * 32 + k];
        wo[k] = whh[(3 * 32 + l) * 32 + k];
    }
    float h = 0.f, c = 0.f;
    const float4* xgp = (const float4*)(xg + (size_t)b * TSEQ * 128) + l;
    for (int ts = 0; ts < TSEQ; ts++) {
        float4 a = xgp[(size_t)ts * 32];
        float gi0 = a.x, gf0 = a.y, gg0 = a.z, go0 = a.w;
        float gi1 = 0.f, gf1 = 0.f, gg1 = 0.f, go1 = 0.f;
#pragma unroll
        for (int k = 0; k < 16; k++) {
            float hk = __shfl_sync(0xffffffffu, h, k);
            gi0 += wi[k] * hk; gf0 += wf[k] * hk;
            gg0 += wg[k] * hk; go0 += wo[k] * hk;
            float hk2 = __shfl_sync(0xffffffffu, h, k + 16);
            gi1 += wi[k + 16] * hk2; gf1 += wf[k + 16] * hk2;
            gg1 += wg[k + 16] * hk2; go1 += wo[k + 16] * hk2;
        }
        c = sigf(gf0 + gf1) * c + sigf(gi0 + gi1) * tanha(gg0 + gg1);
        h = sigf(go0 + go1) * tanha(c);
        if (hout) hout[((size_t)b * TSEQ + ts) * 32 + l] = h;
    }
    if (lastout) lastout[b * 32 + l] = h;
}

// ---------------------------------------------------------------------------
// LSTM scan, H=16: two batches per warp (half-warps), shfl width 16.
// ---------------------------------------------------------------------------
__global__ __launch_bounds__(32) void k_scan16(const float* __restrict__ xg,
                                               const float* __restrict__ whh,
                                               float* __restrict__ hout) {
    const int lane = threadIdx.x;
    const int u = lane & 15;
    const int b = blockIdx.x * 2 + (lane >> 4);
    float wi[16], wf[16], wg[16], wo[16];
#pragma unroll
    for (int k = 0; k < 16; k++) {
        wi[k] = whh[(0 * 16 + u) * 16 + k];
        wf[k] = whh[(1 * 16 + u) * 16 + k];
        wg[k] = whh[(2 * 16 + u) * 16 + k];
        wo[k] = whh[(3 * 16 + u) * 16 + k];
    }
    float h = 0.f, c = 0.f;
    const float4* xgp = (const float4*)(xg + (size_t)b * TSEQ * 64) + u;
    for (int ts = 0; ts < TSEQ; ts++) {
        float4 a = xgp[(size_t)ts * 16];
        float gi = a.x, gf = a.y, gg = a.z, go = a.w;
#pragma unroll
        for (int k = 0; k < 16; k++) {
            float hk = __shfl_sync(0xffffffffu, h, k, 16);
            gi += wi[k] * hk; gf += wf[k] * hk;
            gg += wg[k] * hk; go += wo[k] * hk;
        }
        c = sigf(gf) * c + sigf(gi) * tanha(gg);
        h = sigf(go) * tanha(c);
        hout[((size_t)b * TSEQ + ts) * 16 + u] = h;
    }
}

// ---------------------------------------------------------------------------
extern "C" void kernel_launch(void* const* d_in, const int* in_sizes, int n_in,
                              void* d_out, int out_size) {
    const float* x      = (const float*)d_in[0];
    const float* conv_w = (const float*)d_in[1];
    const float* conv_b = (const float*)d_in[2];
    const float* Wih1   = (const float*)d_in[3];
    const float* Whh1   = (const float*)d_in[4];
    const float* bih1   = (const float*)d_in[5];
    const float* bhh1   = (const float*)d_in[6];
    const float* Wih2   = (const float*)d_in[7];
    const float* Whh2   = (const float*)d_in[8];
    const float* bih2   = (const float*)d_in[9];
    const float* bhh2   = (const float*)d_in[10];
    const float* Wih3   = (const float*)d_in[11];
    const float* Whh3   = (const float*)d_in[12];
    const float* bih3   = (const float*)d_in[13];
    const float* bhh3   = (const float*)d_in[14];
    float* out = (float*)d_out;

    float *p_conv, *p_xg1, *p_h1, *p_xg2, *p_h2, *p_xg3;
    float *p_w1p, *p_b1p, *p_w2p, *p_b2p, *p_w3p, *p_b3p;
    cudaGetSymbolAddress((void**)&p_conv, g_conv);
    cudaGetSymbolAddress((void**)&p_xg1,  g_xg1);
    cudaGetSymbolAddress((void**)&p_h1,   g_h1);
    cudaGetSymbolAddress((void**)&p_xg2,  g_xg2);
    cudaGetSymbolAddress((void**)&p_h2,   g_h2);
    cudaGetSymbolAddress((void**)&p_xg3,  g_xg3);
    cudaGetSymbolAddress((void**)&p_w1p,  g_w1p);
    cudaGetSymbolAddress((void**)&p_b1p,  g_b1p);
    cudaGetSymbolAddress((void**)&p_w2p,  g_w2p);
    cudaGetSymbolAddress((void**)&p_b2p,  g_b2p);
    cudaGetSymbolAddress((void**)&p_w3p,  g_w3p);
    cudaGetSymbolAddress((void**)&p_b3p,  g_b3p);

    // Weight/bias gate permutation (tiny)
    k_perm<<<64, 256>>>(Wih1, bih1, bhh1, p_w1p, p_b1p, 32, 128);
    k_perm<<<8,  256>>>(Wih2, bih2, bhh2, p_w2p, p_b2p, 16, 32);
    k_perm<<<8,  256>>>(Wih3, bih3, bhh3, p_w3p, p_b3p, 32, 16);

    // Conv: [512,128,1024] -> [512,128,1020]
    {
        dim3 grid(16, 2, BATCH);   // 16 l-tiles (64), 2 oc-tiles (64), per-batch
        k_conv<<<grid, 256>>>(x, conv_w, conv_b, p_conv);
    }

    const int GB = MROWS / 64;     // 8160 row-tiles

    // Layer 1: xg1 = conv(as [M][128]) @ W1p^T + b1p ; scan H=32
    k_gemm<128, 128><<<GB, 256>>>(p_conv, p_w1p, p_b1p, p_xg1);
    k_scan32<<<BATCH, 32>>>(p_xg1, Whh1, p_h1, nullptr);

    // Layer 2: xg2 = h1 @ W2p^T + b2p ; scan H=16
    k_gemm<64, 32><<<GB, 256>>>(p_h1, p_w2p, p_b2p, p_xg2);
    k_scan16<<<BATCH / 2, 32>>>(p_xg2, Whh2, p_h2);

    // Layer 3: xg3 = h2 @ W3p^T + b3p ; scan H=32, emit only final h -> d_out
    k_gemm<128, 16><<<GB, 256>>>(p_h2, p_w3p, p_b3p, p_xg3);
    k_scan32<<<BATCH, 32>>>(p_xg3, Whh3, nullptr, out);
}

// round 9
// speedup vs baseline: 1.4513x; 1.4513x over previous
#include <cuda_runtime.h>
#include <cuda_bf16.h>
#include <cstdint>

#define BATCH 512
#define TSEQ  1020
#define MROWS (BATCH * TSEQ)   // 522240

// ---------------- device scratch (no runtime allocation) ----------------
__device__ __align__(256) __nv_bfloat16 g_ch [66846720]; // conv out hi, [b][oc][l] flat
__device__ __align__(256) __nv_bfloat16 g_cl [66846720]; // conv out lo
__device__ __align__(256) float g_xg1 [66846720];  // [M][128] gate-permuted
__device__ __align__(256) float g_h1  [16711680];  // [M][32]
__device__ __align__(256) float g_xg2 [33423360];  // [M][64]
__device__ __align__(256) float g_h2  [ 8355840];  // [M][16]
__device__ __align__(256) float g_xg3 [66846720];  // [M][128]
__device__ __align__(256) float g_w1p [16384];
__device__ __align__(256) float g_b1p [128];
__device__ __align__(256) float g_w2p [2048];
__device__ __align__(256) float g_b2p [64];
__device__ __align__(256) float g_w3p [2048];
__device__ __align__(256) float g_b3p [128];
__device__ __align__(256) __nv_bfloat16 g_wch[81920]; // conv W hi [tap][oc][ic]
__device__ __align__(256) __nv_bfloat16 g_wcl[81920];
__device__ __align__(256) __nv_bfloat16 g_w1h[16384]; // Wih1 perm hi [gate][k]
__device__ __align__(256) __nv_bfloat16 g_w1l[16384];

__device__ __forceinline__ float sigf(float x){ return __fdividef(1.0f, 1.0f + __expf(-x)); }
__device__ __forceinline__ float tanha(float x){ return 2.0f*__fdividef(1.0f,1.0f+__expf(-2.0f*x)) - 1.0f; }
__device__ __forceinline__ void splitbf(float v, __nv_bfloat16& h, __nv_bfloat16& l){
    h = __float2bfloat16(v);
    l = __float2bfloat16(v - __bfloat162float(h));
}
__device__ __forceinline__ uint32_t packbf(__nv_bfloat16 a, __nv_bfloat16 b){
    return (uint32_t)__bfloat16_as_ushort(a) | ((uint32_t)__bfloat16_as_ushort(b) << 16);
}

// m16n8k16 bf16 MMA, f32 accum (sm_80+, target-portable; HMMA on sm_103)
#define MMA16816(c, a, b) \
    asm volatile("mma.sync.aligned.m16n8k16.row.col.f32.bf16.bf16.f32 " \
                 "{%0,%1,%2,%3},{%4,%5,%6,%7},{%8,%9},{%0,%1,%2,%3};" \
                 : "+f"((c)[0]), "+f"((c)[1]), "+f"((c)[2]), "+f"((c)[3]) \
                 : "r"((a)[0]), "r"((a)[1]), "r"((a)[2]), "r"((a)[3]), \
                   "r"((b)[0]), "r"((b)[1]))

// ---------------- small prep kernels ----------------
__global__ void k_perm(const float* __restrict__ Wih, const float* __restrict__ bih,
                       const float* __restrict__ bhh, float* __restrict__ Wp,
                       float* __restrict__ bp, int H, int K) {
    int idx = blockIdx.x * 256 + threadIdx.x;
    int N = 4 * H;
    if (idx < N * K) {
        int p = idx / K, k = idx % K;
        int j = p & 3, l = p >> 2;
        Wp[idx] = Wih[(j * H + l) * K + k];
    }
    if (idx < N) {
        int j = idx & 3, l = idx >> 2;
        bp[idx] = bih[j * H + l] + bhh[j * H + l];
    }
}
__global__ void k_wconvsplit(const float* __restrict__ w,
                             __nv_bfloat16* __restrict__ wh, __nv_bfloat16* __restrict__ wl) {
    int idx = blockIdx.x * 256 + threadIdx.x;
    if (idx >= 81920) return;
    int k = idx / 16384, rem = idx % 16384, oc = rem / 128, ic = rem % 128;
    __nv_bfloat16 h, l; splitbf(w[oc * 640 + ic * 5 + k], h, l);
    wh[idx] = h; wl[idx] = l;
}
__global__ void k_w1split(const float* __restrict__ w,
                          __nv_bfloat16* __restrict__ wh, __nv_bfloat16* __restrict__ wl) {
    int idx = blockIdx.x * 256 + threadIdx.x;
    if (idx >= 16384) return;
    __nv_bfloat16 h, l; splitbf(w[idx], h, l);
    wh[idx] = h; wl[idx] = l;
}

// ---------------- HMMA conv: C[oc][l] = sum_{tap} W_tap @ X(shift tap) ----------------
// grid (8 l-tiles of 128, 512 batches), 256 threads (8 warps of 64oc x 32l).
// smem (bytes): xs fp32 [128][133] @0 (68096); XTh [132][136]bf16 @68096 (35904);
//   XTl @104000; ASh [128][136]bf16 @139904 (34816); ASl @174720. total 209536.
#define CXS   0
#define CXTH  68096
#define CXTL  104000
#define CASH  139904
#define CASL  174720
#define CSMEM 209536
__global__ __launch_bounds__(256) void k_convh(const float* __restrict__ x,
        const __nv_bfloat16* __restrict__ wh, const __nv_bfloat16* __restrict__ wl,
        const float* __restrict__ cb,
        __nv_bfloat16* __restrict__ ch, __nv_bfloat16* __restrict__ cl) {
    extern __shared__ char sm[];
    float* xs = (float*)(sm + CXS);
    const int t = threadIdx.x, warp = t >> 5, lane = t & 31;
    const int g = lane >> 2, tid4 = lane & 3;
    const int wm = warp >> 2;      // 0..1 : oc group of 64
    const int wn = warp & 3;       // 0..3 : l group of 32
    const int l0 = blockIdx.x * 128, b = blockIdx.y;

    // stage x tile fp32 [128 ic][132 cols] (pitch 133 floats, conflict-free col reads)
    for (int i = t; i < 128 * 132; i += 256) {
        int ic = i / 132, col = i - ic * 132;
        int gc = l0 + col;
        xs[ic * 133 + col] = (gc < 1024) ? x[(size_t)b * 131072 + ic * 1024 + gc] : 0.f;
    }
    __syncthreads();
    // build split transpose XT[l][ic] (pitch 272B) once; taps become row offsets
    for (int i = t; i < 132 * 64; i += 256) {
        int l = i >> 6, icp = i & 63;
        float v0 = xs[(2 * icp) * 133 + l];
        float v1 = xs[(2 * icp + 1) * 133 + l];
        __nv_bfloat16 h0, q0, h1, q1;
        splitbf(v0, h0, q0); splitbf(v1, h1, q1);
        *(uint32_t*)(sm + CXTH + l * 272 + icp * 4) = packbf(h0, h1);
        *(uint32_t*)(sm + CXTL + l * 272 + icp * 4) = packbf(q0, q1);
    }
    __syncthreads();

    float c[4][4][4];
#pragma unroll
    for (int mt = 0; mt < 4; mt++)
#pragma unroll
        for (int nt = 0; nt < 4; nt++)
#pragma unroll
            for (int j = 0; j < 4; j++) c[mt][nt][j] = 0.f;

#pragma unroll 1
    for (int tap = 0; tap < 5; tap++) {
        // stage W_tap hi/lo [128 oc][128 ic] -> pitch-272 smem
        for (int i = t; i < 2048; i += 256) {
            int row = i >> 4, q = i & 15;
            *(uint4*)(sm + CASH + row * 272 + q * 16) =
                *(const uint4*)(wh + tap * 16384 + row * 128 + q * 8);
            *(uint4*)(sm + CASL + row * 272 + q * 16) =
                *(const uint4*)(wl + tap * 16384 + row * 128 + q * 8);
        }
        __syncthreads();
#pragma unroll 1
        for (int term = 0; term < 3; term++) {
            const char* ab = sm + (term == 1 ? CASL : CASH);
            const char* bb = sm + (term == 2 ? CXTL : CXTH);
#pragma unroll
            for (int kc = 0; kc < 8; kc++) {
                uint32_t a[4][4], bf[4][2];
                const int kb = kc * 32 + tid4 * 4;
#pragma unroll
                for (int mt = 0; mt < 4; mt++) {
                    const char* p = ab + (wm * 64 + mt * 16 + g) * 272 + kb;
                    a[mt][0] = *(const uint32_t*)(p);
                    a[mt][1] = *(const uint32_t*)(p + 8 * 272);
                    a[mt][2] = *(const uint32_t*)(p + 16);
                    a[mt][3] = *(const uint32_t*)(p + 8 * 272 + 16);
                }
#pragma unroll
                for (int nt = 0; nt < 4; nt++) {
                    const char* p = bb + (wn * 32 + nt * 8 + g + tap) * 272 + kb;
                    bf[nt][0] = *(const uint32_t*)(p);
                    bf[nt][1] = *(const uint32_t*)(p + 16);
                }
#pragma unroll
                for (int mt = 0; mt < 4; mt++)
#pragma unroll
                    for (int nt = 0; nt < 4; nt++)
                        MMA16816(c[mt][nt], a[mt], bf[nt]);
            }
        }
        __syncthreads();
    }

    // epilogue: +bias, split to bf16 hi/lo, store [b][oc][l]
#pragma unroll
    for (int mt = 0; mt < 4; mt++) {
        int oc = wm * 64 + mt * 16 + g;
        float b0 = __ldg(&cb[oc]), b8 = __ldg(&cb[oc + 8]);
        size_t r0 = ((size_t)b * 128 + oc) * 1020;
        size_t r8 = r0 + 8 * 1020;
#pragma unroll
        for (int nt = 0; nt < 4; nt++) {
            int lg = l0 + wn * 32 + nt * 8 + 2 * tid4;
            if (lg < 1020) {
                float v0 = c[mt][nt][0] + b0, v1 = c[mt][nt][1] + b0;
                float v2 = c[mt][nt][2] + b8, v3 = c[mt][nt][3] + b8;
                __nv_bfloat16 h0, q0, h1, q1, h2, q2, h3, q3;
                splitbf(v0, h0, q0); splitbf(v1, h1, q1);
                splitbf(v2, h2, q2); splitbf(v3, h3, q3);
                *(uint32_t*)&ch[r0 + lg] = packbf(h0, h1);
                *(uint32_t*)&cl[r0 + lg] = packbf(q0, q1);
                *(uint32_t*)&ch[r8 + lg] = packbf(h2, h3);
                *(uint32_t*)&cl[r8 + lg] = packbf(q2, q3);
            }
        }
    }
}

// ---------------- HMMA GEMM1: xg1[m][gate] = A[m][:]·W1p[gate][:] + b ----------------
// grid 4080 (M-tiles of 128), 256 threads (8 warps of 64m x 32n).
// smem: bias 512 @0; ASh @512 (34816); ASl @35328; BSh @70144; BSl @104960. total 139776.
#define G_BI  0
#define G_ASH 512
#define G_ASL 35328
#define G_BSH 70144
#define G_BSL 104960
#define G_SMEM 139776
__global__ __launch_bounds__(256) void k_g1h(const __nv_bfloat16* __restrict__ ah,
        const __nv_bfloat16* __restrict__ al,
        const __nv_bfloat16* __restrict__ w1h, const __nv_bfloat16* __restrict__ w1l,
        const float* __restrict__ bp, float* __restrict__ xg) {
    extern __shared__ char sm[];
    float* bs = (float*)(sm + G_BI);
    const int t = threadIdx.x, warp = t >> 5, lane = t & 31;
    const int g = lane >> 2, tid4 = lane & 3;
    const int wm = warp >> 2;      // 0..1 : m group of 64
    const int wn = warp & 3;       // 0..3 : n group of 32
    const size_t m0 = (size_t)blockIdx.x * 128;

    if (t < 128) bs[t] = bp[t];
    for (int i = t; i < 2048; i += 256) {
        int row = i >> 4, q = i & 15;
        *(uint4*)(sm + G_ASH + row * 272 + q * 16) = *(const uint4*)(ah + (m0 + row) * 128 + q * 8);
        *(uint4*)(sm + G_ASL + row * 272 + q * 16) = *(const uint4*)(al + (m0 + row) * 128 + q * 8);
        *(uint4*)(sm + G_BSH + row * 272 + q * 16) = *(const uint4*)(w1h + row * 128 + q * 8);
        *(uint4*)(sm + G_BSL + row * 272 + q * 16) = *(const uint4*)(w1l + row * 128 + q * 8);
    }
    __syncthreads();

    float c[4][4][4];
#pragma unroll
    for (int mt = 0; mt < 4; mt++)
#pragma unroll
        for (int nt = 0; nt < 4; nt++)
#pragma unroll
            for (int j = 0; j < 4; j++) c[mt][nt][j] = 0.f;

#pragma unroll 1
    for (int term = 0; term < 3; term++) {
        const char* ab = sm + (term == 1 ? G_ASL : G_ASH);
        const char* bb = sm + (term == 2 ? G_BSL : G_BSH);
#pragma unroll
        for (int kc = 0; kc < 8; kc++) {
            uint32_t a[4][4], bf[4][2];
            const int kb = kc * 32 + tid4 * 4;
#pragma unroll
            for (int mt = 0; mt < 4; mt++) {
                const char* p = ab + (wm * 64 + mt * 16 + g) * 272 + kb;
                a[mt][0] = *(const uint32_t*)(p);
                a[mt][1] = *(const uint32_t*)(p + 8 * 272);
                a[mt][2] = *(const uint32_t*)(p + 16);
                a[mt][3] = *(const uint32_t*)(p + 8 * 272 + 16);
            }
#pragma unroll
            for (int nt = 0; nt < 4; nt++) {
                const char* p = bb + (wn * 32 + nt * 8 + g) * 272 + kb;
                bf[nt][0] = *(const uint32_t*)(p);
                bf[nt][1] = *(const uint32_t*)(p + 16);
            }
#pragma unroll
            for (int mt = 0; mt < 4; mt++)
#pragma unroll
                for (int nt = 0; nt < 4; nt++)
                    MMA16816(c[mt][nt], a[mt], bf[nt]);
        }
    }

#pragma unroll
    for (int mt = 0; mt < 4; mt++) {
        size_t m = m0 + wm * 64 + mt * 16 + g;
#pragma unroll
        for (int nt = 0; nt < 4; nt++) {
            int col = wn * 32 + nt * 8 + 2 * tid4;
            float bx = bs[col], by = bs[col + 1];
            float2 o0 = { c[mt][nt][0] + bx, c[mt][nt][1] + by };
            float2 o1 = { c[mt][nt][2] + bx, c[mt][nt][3] + by };
            *(float2*)&xg[m * 128 + col] = o0;
            *(float2*)&xg[(m + 8) * 128 + col] = o1;
        }
    }
}

// ---------------- fp32 GEMM for layers 2/3 ----------------
template <int N, int K>
__global__ __launch_bounds__(256) void k_gemm(const float* __restrict__ A,
                                              const float* __restrict__ Wp,
                                              const float* __restrict__ bp,
                                              float* __restrict__ Xg) {
    constexpr int KC = 16;
    constexpr int CG = N / 4;
    constexpr int RG = 256 / CG;
    constexpr int RPT = 64 / RG;
    __shared__ float As[64][KC];
    __shared__ float Ws[KC][N];
    const int t = threadIdx.x;
    const int cg = t % CG, rg = t / CG;
    const size_t m0 = (size_t)blockIdx.x * 64;
    float acc[RPT][4];
#pragma unroll
    for (int r = 0; r < RPT; r++)
#pragma unroll
        for (int j = 0; j < 4; j++) acc[r][j] = 0.f;
    for (int kc = 0; kc < K; kc += KC) {
        {
            int row = t >> 2, k4 = (t & 3) * 4;
            *(float4*)&As[row][k4] = *(const float4*)&A[(m0 + row) * K + kc + k4];
        }
#pragma unroll
        for (int e = 0; e < N * KC / 256; e++) {
            int idx = t + e * 256;
            int p = idx % N, kk = idx / N;
            Ws[kk][p] = Wp[p * K + kc + kk];
        }
        __syncthreads();
#pragma unroll
        for (int kk = 0; kk < KC; kk++) {
            float4 w4 = *(const float4*)&Ws[kk][cg * 4];
#pragma unroll
            for (int r = 0; r < RPT; r++) {
                float av = As[rg * RPT + r][kk];
                acc[r][0] += av * w4.x; acc[r][1] += av * w4.y;
                acc[r][2] += av * w4.z; acc[r][3] += av * w4.w;
            }
        }
        __syncthreads();
    }
    float4 bv = *(const float4*)&bp[cg * 4];
#pragma unroll
    for (int r = 0; r < RPT; r++) {
        size_t m = m0 + rg * RPT + r;
        float4 o = { acc[r][0] + bv.x, acc[r][1] + bv.y, acc[r][2] + bv.z, acc[r][3] + bv.w };
        *(float4*)&Xg[m * N + cg * 4] = o;
    }
}

// ---------------- LSTM scans ----------------
__global__ __launch_bounds__(32) void k_scan32(const float* __restrict__ xg,
                                               const float* __restrict__ whh,
                                               float* __restrict__ hout,
                                               float* __restrict__ lastout) {
    const int b = blockIdx.x, l = threadIdx.x;
    float wi[32], wf[32], wg[32], wo[32];
#pragma unroll
    for (int k = 0; k < 32; k++) {
        wi[k] = whh[(0 * 32 + l) * 32 + k];
        wf[k] = whh[(1 * 32 + l) * 32 + k];
        wg[k] = whh[(2 * 32 + l) * 32 + k];
        wo[k] = whh[(3 * 32 + l) * 32 + k];
    }
    float h = 0.f, c = 0.f;
    const float4* xgp = (const float4*)(xg + (size_t)b * TSEQ * 128) + l;
    for (int ts = 0; ts < TSEQ; ts++) {
        float4 a = xgp[(size_t)ts * 32];
        float gi0 = a.x, gf0 = a.y, gg0 = a.z, go0 = a.w;
        float gi1 = 0.f, gf1 = 0.f, gg1 = 0.f, go1 = 0.f;
#pragma unroll
        for (int k = 0; k < 16; k++) {
            float hk = __shfl_sync(0xffffffffu, h, k);
            gi0 += wi[k] * hk; gf0 += wf[k] * hk; gg0 += wg[k] * hk; go0 += wo[k] * hk;
            float hk2 = __shfl_sync(0xffffffffu, h, k + 16);
            gi1 += wi[k+16] * hk2; gf1 += wf[k+16] * hk2; gg1 += wg[k+16] * hk2; go1 += wo[k+16] * hk2;
        }
        c = sigf(gf0 + gf1) * c + sigf(gi0 + gi1) * tanha(gg0 + gg1);
        h = sigf(go0 + go1) * tanha(c);
        if (hout) hout[((size_t)b * TSEQ + ts) * 32 + l] = h;
    }
    if (lastout) lastout[b * 32 + l] = h;
}
__global__ __launch_bounds__(32) void k_scan16(const float* __restrict__ xg,
                                               const float* __restrict__ whh,
                                               float* __restrict__ hout) {
    const int lane = threadIdx.x;
    const int u = lane & 15;
    const int b = blockIdx.x * 2 + (lane >> 4);
    float wi[16], wf[16], wg[16], wo[16];
#pragma unroll
    for (int k = 0; k < 16; k++) {
        wi[k] = whh[(0 * 16 + u) * 16 + k];
        wf[k] = whh[(1 * 16 + u) * 16 + k];
        wg[k] = whh[(2 * 16 + u) * 16 + k];
        wo[k] = whh[(3 * 16 + u) * 16 + k];
    }
    float h = 0.f, c = 0.f;
    const float4* xgp = (const float4*)(xg + (size_t)b * TSEQ * 64) + u;
    for (int ts = 0; ts < TSEQ; ts++) {
        float4 a = xgp[(size_t)ts * 16];
        float gi = a.x, gf = a.y, gg = a.z, go = a.w;
#pragma unroll
        for (int k = 0; k < 16; k++) {
            float hk = __shfl_sync(0xffffffffu, h, k, 16);
            gi += wi[k] * hk; gf += wf[k] * hk; gg += wg[k] * hk; go += wo[k] * hk;
        }
        c = sigf(gf) * c + sigf(gi) * tanha(gg);
        h = sigf(go) * tanha(c);
        hout[((size_t)b * TSEQ + ts) * 16 + u] = h;
    }
}

// ---------------- launch ----------------
extern "C" void kernel_launch(void* const* d_in, const int* in_sizes, int n_in,
                              void* d_out, int out_size) {
    const float* x      = (const float*)d_in[0];
    const float* conv_w = (const float*)d_in[1];
    const float* conv_b = (const float*)d_in[2];
    const float* Wih1   = (const float*)d_in[3];
    const float* Whh1   = (const float*)d_in[4];
    const float* bih1   = (const float*)d_in[5];
    const float* bhh1   = (const float*)d_in[6];
    const float* Wih2   = (const float*)d_in[7];
    const float* Whh2   = (const float*)d_in[8];
    const float* bih2   = (const float*)d_in[9];
    const float* bhh2   = (const float*)d_in[10];
    const float* Wih3   = (const float*)d_in[11];
    const float* Whh3   = (const float*)d_in[12];
    const float* bih3   = (const float*)d_in[13];
    const float* bhh3   = (const float*)d_in[14];
    float* out = (float*)d_out;

    __nv_bfloat16 *p_ch, *p_cl, *p_wch, *p_wcl, *p_w1h, *p_w1l;
    float *p_xg1, *p_h1, *p_xg2, *p_h2, *p_xg3;
    float *p_w1p, *p_b1p, *p_w2p, *p_b2p, *p_w3p, *p_b3p;
    cudaGetSymbolAddress((void**)&p_ch,  g_ch);
    cudaGetSymbolAddress((void**)&p_cl,  g_cl);
    cudaGetSymbolAddress((void**)&p_wch, g_wch);
    cudaGetSymbolAddress((void**)&p_wcl, g_wcl);
    cudaGetSymbolAddress((void**)&p_w1h, g_w1h);
    cudaGetSymbolAddress((void**)&p_w1l, g_w1l);
    cudaGetSymbolAddress((void**)&p_xg1, g_xg1);
    cudaGetSymbolAddress((void**)&p_h1,  g_h1);
    cudaGetSymbolAddress((void**)&p_xg2, g_xg2);
    cudaGetSymbolAddress((void**)&p_h2,  g_h2);
    cudaGetSymbolAddress((void**)&p_xg3, g_xg3);
    cudaGetSymbolAddress((void**)&p_w1p, g_w1p);
    cudaGetSymbolAddress((void**)&p_b1p, g_b1p);
    cudaGetSymbolAddress((void**)&p_w2p, g_w2p);
    cudaGetSymbolAddress((void**)&p_b2p, g_b2p);
    cudaGetSymbolAddress((void**)&p_w3p, g_w3p);
    cudaGetSymbolAddress((void**)&p_b3p, g_b3p);

    cudaFuncSetAttribute(k_convh, cudaFuncAttributeMaxDynamicSharedMemorySize, CSMEM);
    cudaFuncSetAttribute(k_g1h,   cudaFuncAttributeMaxDynamicSharedMemorySize, G_SMEM);

    // prep (tiny)
    k_perm<<<64, 256>>>(Wih1, bih1, bhh1, p_w1p, p_b1p, 32, 128);
    k_perm<<<8,  256>>>(Wih2, bih2, bhh2, p_w2p, p_b2p, 16, 32);
    k_perm<<<8,  256>>>(Wih3, bih3, bhh3, p_w3p, p_b3p, 32, 16);
    k_wconvsplit<<<320, 256>>>(conv_w, p_wch, p_wcl);
    k_w1split<<<64, 256>>>(p_w1p, p_w1h, p_w1l);

    // conv (HMMA, 3-term bf16 split) -> bf16 hi/lo conv output
    {
        dim3 g(8, BATCH);
        k_convh<<<g, 256, CSMEM>>>(x, p_wch, p_wcl, conv_b, p_ch, p_cl);
    }
    // layer 1: xg1 (HMMA) ; scan H=32
    k_g1h<<<MROWS / 128, 256, G_SMEM>>>(p_ch, p_cl, p_w1h, p_w1l, p_b1p, p_xg1);
    k_scan32<<<BATCH, 32>>>(p_xg1, Whh1, p_h1, nullptr);
    // layer 2
    k_gemm<64, 32><<<MROWS / 64, 256>>>(p_h1, p_w2p, p_b2p, p_xg2);
    k_scan16<<<BATCH / 2, 32>>>(p_xg2, Whh2, p_h2);
    // layer 3
    k_gemm<128, 16><<<MROWS / 64, 256>>>(p_h2, p_w3p, p_b3p, p_xg3);
    k_scan32<<<BATCH, 32>>>(p_xg3, Whh3, nullptr, out);
}

// round 10
// speedup vs baseline: 1.7214x; 1.1861x over previous
#include <cuda_runtime.h>
#include <cuda_bf16.h>
#include <cstdint>

#define BATCH 512
#define TSEQ  1020
#define MROWS (BATCH * TSEQ)   // 522240

// ---------------- device scratch (no runtime allocation) ----------------
__device__ __align__(256) __nv_bfloat16 g_ch [66846720]; // conv out hi, [b][oc][l] flat
__device__ __align__(256) __nv_bfloat16 g_cl [66846720]; // conv out lo
__device__ __align__(256) float g_xg1 [66846720];  // [M][128] gate-permuted
__device__ __align__(256) float g_h1  [16711680];  // [M][32]
__device__ __align__(256) float g_xg2 [33423360];  // [M][64]
__device__ __align__(256) float g_h2  [ 8355840];  // [M][16]
__device__ __align__(256) float g_xg3 [66846720];  // [M][128]
__device__ __align__(256) float g_w1p [16384];
__device__ __align__(256) float g_b1p [128];
__device__ __align__(256) float g_w2p [2048];
__device__ __align__(256) float g_b2p [64];
__device__ __align__(256) float g_w3p [2048];
__device__ __align__(256) float g_b3p [128];
__device__ __align__(256) __nv_bfloat16 g_wch[81920]; // conv W hi [tap][oc][ic]
__device__ __align__(256) __nv_bfloat16 g_wcl[81920];
__device__ __align__(256) __nv_bfloat16 g_w1h[16384]; // Wih1 perm hi [gate][k]
__device__ __align__(256) __nv_bfloat16 g_w1l[16384];

__device__ __forceinline__ float sigf(float x){ return __fdividef(1.0f, 1.0f + __expf(-x)); }
__device__ __forceinline__ float tanha(float x){ return 2.0f*__fdividef(1.0f,1.0f+__expf(-2.0f*x)) - 1.0f; }
__device__ __forceinline__ void splitbf(float v, __nv_bfloat16& h, __nv_bfloat16& l){
    h = __float2bfloat16(v);
    l = __float2bfloat16(v - __bfloat162float(h));
}
__device__ __forceinline__ uint32_t packbf(__nv_bfloat16 a, __nv_bfloat16 b){
    return (uint32_t)__bfloat16_as_ushort(a) | ((uint32_t)__bfloat16_as_ushort(b) << 16);
}

// m16n8k16 bf16 MMA, f32 accum (sm_80+, target-portable; HMMA on sm_103)
#define MMA16816(c, a, b) \
    asm volatile("mma.sync.aligned.m16n8k16.row.col.f32.bf16.bf16.f32 " \
                 "{%0,%1,%2,%3},{%4,%5,%6,%7},{%8,%9},{%0,%1,%2,%3};" \
                 : "+f"((c)[0]), "+f"((c)[1]), "+f"((c)[2]), "+f"((c)[3]) \
                 : "r"((a)[0]), "r"((a)[1]), "r"((a)[2]), "r"((a)[3]), \
                   "r"((b)[0]), "r"((b)[1]))

// ---------------- small prep kernels ----------------
__global__ void k_perm(const float* __restrict__ Wih, const float* __restrict__ bih,
                       const float* __restrict__ bhh, float* __restrict__ Wp,
                       float* __restrict__ bp, int H, int K) {
    int idx = blockIdx.x * 256 + threadIdx.x;
    int N = 4 * H;
    if (idx < N * K) {
        int p = idx / K, k = idx % K;
        int j = p & 3, l = p >> 2;
        Wp[idx] = Wih[(j * H + l) * K + k];
    }
    if (idx < N) {
        int j = idx & 3, l = idx >> 2;
        bp[idx] = bih[j * H + l] + bhh[j * H + l];
    }
}
__global__ void k_wconvsplit(const float* __restrict__ w,
                             __nv_bfloat16* __restrict__ wh, __nv_bfloat16* __restrict__ wl) {
    int idx = blockIdx.x * 256 + threadIdx.x;
    if (idx >= 81920) return;
    int k = idx / 16384, rem = idx % 16384, oc = rem / 128, ic = rem % 128;
    __nv_bfloat16 h, l; splitbf(w[oc * 640 + ic * 5 + k], h, l);
    wh[idx] = h; wl[idx] = l;
}
__global__ void k_w1split(const float* __restrict__ w,
                          __nv_bfloat16* __restrict__ wh, __nv_bfloat16* __restrict__ wl) {
    int idx = blockIdx.x * 256 + threadIdx.x;
    if (idx >= 16384) return;
    __nv_bfloat16 h, l; splitbf(w[idx], h, l);
    wh[idx] = h; wl[idx] = l;
}

// ---------------- HMMA conv: C[oc][l] = sum_{tap} W_tap @ X(shift tap) ----------------
// grid (8 l-tiles of 128, 512 batches), 256 threads (8 warps of 64oc x 32l).
#define CXS   0
#define CXTH  68096
#define CXTL  104000
#define CASH  139904
#define CASL  174720
#define CSMEM 209536
__global__ __launch_bounds__(256) void k_convh(const float* __restrict__ x,
        const __nv_bfloat16* __restrict__ wh, const __nv_bfloat16* __restrict__ wl,
        const float* __restrict__ cb,
        __nv_bfloat16* __restrict__ ch, __nv_bfloat16* __restrict__ cl) {
    extern __shared__ char sm[];
    float* xs = (float*)(sm + CXS);
    const int t = threadIdx.x, warp = t >> 5, lane = t & 31;
    const int g = lane >> 2, tid4 = lane & 3;
    const int wm = warp >> 2;      // 0..1 : oc group of 64
    const int wn = warp & 3;       // 0..3 : l group of 32
    const int l0 = blockIdx.x * 128, b = blockIdx.y;

    // stage x tile fp32 [128 ic][132 cols]
    for (int i = t; i < 128 * 132; i += 256) {
        int ic = i / 132, col = i - ic * 132;
        int gc = l0 + col;
        xs[ic * 133 + col] = (gc < 1024) ? x[(size_t)b * 131072 + ic * 1024 + gc] : 0.f;
    }
    __syncthreads();
    // build split transpose XT[l][ic] (pitch 272B) once; taps become row offsets
    for (int i = t; i < 132 * 64; i += 256) {
        int l = i >> 6, icp = i & 63;
        float v0 = xs[(2 * icp) * 133 + l];
        float v1 = xs[(2 * icp + 1) * 133 + l];
        __nv_bfloat16 h0, q0, h1, q1;
        splitbf(v0, h0, q0); splitbf(v1, h1, q1);
        *(uint32_t*)(sm + CXTH + l * 272 + icp * 4) = packbf(h0, h1);
        *(uint32_t*)(sm + CXTL + l * 272 + icp * 4) = packbf(q0, q1);
    }
    __syncthreads();

    float c[4][4][4];
#pragma unroll
    for (int mt = 0; mt < 4; mt++)
#pragma unroll
        for (int nt = 0; nt < 4; nt++)
#pragma unroll
            for (int j = 0; j < 4; j++) c[mt][nt][j] = 0.f;

#pragma unroll 1
    for (int tap = 0; tap < 5; tap++) {
        for (int i = t; i < 2048; i += 256) {
            int row = i >> 4, q = i & 15;
            *(uint4*)(sm + CASH + row * 272 + q * 16) =
                *(const uint4*)(wh + tap * 16384 + row * 128 + q * 8);
            *(uint4*)(sm + CASL + row * 272 + q * 16) =
                *(const uint4*)(wl + tap * 16384 + row * 128 + q * 8);
        }
        __syncthreads();
#pragma unroll 1
        for (int term = 0; term < 3; term++) {
            const char* ab = sm + (term == 1 ? CASL : CASH);
            const char* bb = sm + (term == 2 ? CXTL : CXTH);
#pragma unroll
            for (int kc = 0; kc < 8; kc++) {
                uint32_t a[4][4], bf[4][2];
                const int kb = kc * 32 + tid4 * 4;
#pragma unroll
                for (int mt = 0; mt < 4; mt++) {
                    const char* p = ab + (wm * 64 + mt * 16 + g) * 272 + kb;
                    a[mt][0] = *(const uint32_t*)(p);
                    a[mt][1] = *(const uint32_t*)(p + 8 * 272);
                    a[mt][2] = *(const uint32_t*)(p + 16);
                    a[mt][3] = *(const uint32_t*)(p + 8 * 272 + 16);
                }
#pragma unroll
                for (int nt = 0; nt < 4; nt++) {
                    const char* p = bb + (wn * 32 + nt * 8 + g + tap) * 272 + kb;
                    bf[nt][0] = *(const uint32_t*)(p);
                    bf[nt][1] = *(const uint32_t*)(p + 16);
                }
#pragma unroll
                for (int mt = 0; mt < 4; mt++)
#pragma unroll
                    for (int nt = 0; nt < 4; nt++)
                        MMA16816(c[mt][nt], a[mt], bf[nt]);
            }
        }
        __syncthreads();
    }

    // epilogue: +bias, split to bf16 hi/lo, store [b][oc][l]
#pragma unroll
    for (int mt = 0; mt < 4; mt++) {
        int oc = wm * 64 + mt * 16 + g;
        float b0 = __ldg(&cb[oc]), b8 = __ldg(&cb[oc + 8]);
        size_t r0 = ((size_t)b * 128 + oc) * 1020;
        size_t r8 = r0 + 8 * 1020;
#pragma unroll
        for (int nt = 0; nt < 4; nt++) {
            int lg = l0 + wn * 32 + nt * 8 + 2 * tid4;
            if (lg < 1020) {
                float v0 = c[mt][nt][0] + b0, v1 = c[mt][nt][1] + b0;
                float v2 = c[mt][nt][2] + b8, v3 = c[mt][nt][3] + b8;
                __nv_bfloat16 h0, q0, h1, q1, h2, q2, h3, q3;
                splitbf(v0, h0, q0); splitbf(v1, h1, q1);
                splitbf(v2, h2, q2); splitbf(v3, h3, q3);
                *(uint32_t*)&ch[r0 + lg] = packbf(h0, h1);
                *(uint32_t*)&cl[r0 + lg] = packbf(q0, q1);
                *(uint32_t*)&ch[r8 + lg] = packbf(h2, h3);
                *(uint32_t*)&cl[r8 + lg] = packbf(q2, q3);
            }
        }
    }
}

// ---------------- HMMA GEMM1: xg1[m][gate] = A[m][:]·W1p[gate][:] + b ----------------
#define G_BI  0
#define G_ASH 512
#define G_ASL 35328
#define G_BSH 70144
#define G_BSL 104960
#define G_SMEM 139776
__global__ __launch_bounds__(256) void k_g1h(const __nv_bfloat16* __restrict__ ah,
        const __nv_bfloat16* __restrict__ al,
        const __nv_bfloat16* __restrict__ w1h, const __nv_bfloat16* __restrict__ w1l,
        const float* __restrict__ bp, float* __restrict__ xg) {
    extern __shared__ char sm[];
    float* bs = (float*)(sm + G_BI);
    const int t = threadIdx.x, warp = t >> 5, lane = t & 31;
    const int g = lane >> 2, tid4 = lane & 3;
    const int wm = warp >> 2;
    const int wn = warp & 3;
    const size_t m0 = (size_t)blockIdx.x * 128;

    if (t < 128) bs[t] = bp[t];
    for (int i = t; i < 2048; i += 256) {
        int row = i >> 4, q = i & 15;
        *(uint4*)(sm + G_ASH + row * 272 + q * 16) = *(const uint4*)(ah + (m0 + row) * 128 + q * 8);
        *(uint4*)(sm + G_ASL + row * 272 + q * 16) = *(const uint4*)(al + (m0 + row) * 128 + q * 8);
        *(uint4*)(sm + G_BSH + row * 272 + q * 16) = *(const uint4*)(w1h + row * 128 + q * 8);
        *(uint4*)(sm + G_BSL + row * 272 + q * 16) = *(const uint4*)(w1l + row * 128 + q * 8);
    }
    __syncthreads();

    float c[4][4][4];
#pragma unroll
    for (int mt = 0; mt < 4; mt++)
#pragma unroll
        for (int nt = 0; nt < 4; nt++)
#pragma unroll
            for (int j = 0; j < 4; j++) c[mt][nt][j] = 0.f;

#pragma unroll 1
    for (int term = 0; term < 3; term++) {
        const char* ab = sm + (term == 1 ? G_ASL : G_ASH);
        const char* bb = sm + (term == 2 ? G_BSL : G_BSH);
#pragma unroll
        for (int kc = 0; kc < 8; kc++) {
            uint32_t a[4][4], bf[4][2];
            const int kb = kc * 32 + tid4 * 4;
#pragma unroll
            for (int mt = 0; mt < 4; mt++) {
                const char* p = ab + (wm * 64 + mt * 16 + g) * 272 + kb;
                a[mt][0] = *(const uint32_t*)(p);
                a[mt][1] = *(const uint32_t*)(p + 8 * 272);
                a[mt][2] = *(const uint32_t*)(p + 16);
                a[mt][3] = *(const uint32_t*)(p + 8 * 272 + 16);
            }
#pragma unroll
            for (int nt = 0; nt < 4; nt++) {
                const char* p = bb + (wn * 32 + nt * 8 + g) * 272 + kb;
                bf[nt][0] = *(const uint32_t*)(p);
                bf[nt][1] = *(const uint32_t*)(p + 16);
            }
#pragma unroll
            for (int mt = 0; mt < 4; mt++)
#pragma unroll
                for (int nt = 0; nt < 4; nt++)
                    MMA16816(c[mt][nt], a[mt], bf[nt]);
        }
    }

#pragma unroll
    for (int mt = 0; mt < 4; mt++) {
        size_t m = m0 + wm * 64 + mt * 16 + g;
#pragma unroll
        for (int nt = 0; nt < 4; nt++) {
            int col = wn * 32 + nt * 8 + 2 * tid4;
            float bx = bs[col], by = bs[col + 1];
            float2 o0 = { c[mt][nt][0] + bx, c[mt][nt][1] + by };
            float2 o1 = { c[mt][nt][2] + bx, c[mt][nt][3] + by };
            *(float2*)&xg[m * 128 + col] = o0;
            *(float2*)&xg[(m + 8) * 128 + col] = o1;
        }
    }
}

// ---------------- fp32 GEMM for layers 2/3 ----------------
template <int N, int K>
__global__ __launch_bounds__(256) void k_gemm(const float* __restrict__ A,
                                              const float* __restrict__ Wp,
                                              const float* __restrict__ bp,
                                              float* __restrict__ Xg) {
    constexpr int KC = 16;
    constexpr int CG = N / 4;
    constexpr int RG = 256 / CG;
    constexpr int RPT = 64 / RG;
    __shared__ float As[64][KC];
    __shared__ float Ws[KC][N];
    const int t = threadIdx.x;
    const int cg = t % CG, rg = t / CG;
    const size_t m0 = (size_t)blockIdx.x * 64;
    float acc[RPT][4];
#pragma unroll
    for (int r = 0; r < RPT; r++)
#pragma unroll
        for (int j = 0; j < 4; j++) acc[r][j] = 0.f;
    for (int kc = 0; kc < K; kc += KC) {
        {
            int row = t >> 2, k4 = (t & 3) * 4;
            *(float4*)&As[row][k4] = *(const float4*)&A[(m0 + row) * K + kc + k4];
        }
#pragma unroll
        for (int e = 0; e < N * KC / 256; e++) {
            int idx = t + e * 256;
            int p = idx % N, kk = idx / N;
            Ws[kk][p] = Wp[p * K + kc + kk];
        }
        __syncthreads();
#pragma unroll
        for (int kk = 0; kk < KC; kk++) {
            float4 w4 = *(const float4*)&Ws[kk][cg * 4];
#pragma unroll
            for (int r = 0; r < RPT; r++) {
                float av = As[rg * RPT + r][kk];
                acc[r][0] += av * w4.x; acc[r][1] += av * w4.y;
                acc[r][2] += av * w4.z; acc[r][3] += av * w4.w;
            }
        }
        __syncthreads();
    }
    float4 bv = *(const float4*)&bp[cg * 4];
#pragma unroll
    for (int r = 0; r < RPT; r++) {
        size_t m = m0 + rg * RPT + r;
        float4 o = { acc[r][0] + bv.x, acc[r][1] + bv.y, acc[r][2] + bv.z, acc[r][3] + bv.w };
        *(float4*)&Xg[m * N + cg * 4] = o;
    }
}

// ---------------- LSTM scans (4-deep register prefetch pipeline) ----------------
__global__ __launch_bounds__(32) void k_scan32(const float* __restrict__ xg,
                                               const float* __restrict__ whh,
                                               float* __restrict__ hout,
                                               float* __restrict__ lastout) {
    const int b = blockIdx.x, l = threadIdx.x;
    float wi[32], wf[32], wg[32], wo[32];
#pragma unroll
    for (int k = 0; k < 32; k++) {
        wi[k] = whh[(0 * 32 + l) * 32 + k];
        wf[k] = whh[(1 * 32 + l) * 32 + k];
        wg[k] = whh[(2 * 32 + l) * 32 + k];
        wo[k] = whh[(3 * 32 + l) * 32 + k];
    }
    float h = 0.f, c = 0.f;
    const float4* xgp = (const float4*)(xg + (size_t)b * TSEQ * 128) + l;
    float4 buf[4];
#pragma unroll
    for (int i = 0; i < 4; i++) buf[i] = xgp[(size_t)i * 32];
    // TSEQ = 1020 = 4*255
    for (int ts = 0; ts < TSEQ; ts += 4) {
#pragma unroll
        for (int j = 0; j < 4; j++) {
            float4 a = buf[j];
            int nts = ts + j + 4;
            if (nts < TSEQ) buf[j] = xgp[(size_t)nts * 32];
            float gi0 = a.x, gf0 = a.y, gg0 = a.z, go0 = a.w;
            float gi1 = 0.f, gf1 = 0.f, gg1 = 0.f, go1 = 0.f;
#pragma unroll
            for (int k = 0; k < 16; k++) {
                float hk = __shfl_sync(0xffffffffu, h, k);
                gi0 += wi[k] * hk; gf0 += wf[k] * hk; gg0 += wg[k] * hk; go0 += wo[k] * hk;
                float hk2 = __shfl_sync(0xffffffffu, h, k + 16);
                gi1 += wi[k+16] * hk2; gf1 += wf[k+16] * hk2; gg1 += wg[k+16] * hk2; go1 += wo[k+16] * hk2;
            }
            c = sigf(gf0 + gf1) * c + sigf(gi0 + gi1) * tanha(gg0 + gg1);
            h = sigf(go0 + go1) * tanha(c);
            if (hout) hout[((size_t)b * TSEQ + ts + j) * 32 + l] = h;
        }
    }
    if (lastout) lastout[b * 32 + l] = h;
}
__global__ __launch_bounds__(32) void k_scan16(const float* __restrict__ xg,
                                               const float* __restrict__ whh,
                                               float* __restrict__ hout) {
    const int lane = threadIdx.x;
    const int u = lane & 15;
    const int b = blockIdx.x * 2 + (lane >> 4);
    float wi[16], wf[16], wg[16], wo[16];
#pragma unroll
    for (int k = 0; k < 16; k++) {
        wi[k] = whh[(0 * 16 + u) * 16 + k];
        wf[k] = whh[(1 * 16 + u) * 16 + k];
        wg[k] = whh[(2 * 16 + u) * 16 + k];
        wo[k] = whh[(3 * 16 + u) * 16 + k];
    }
    float h = 0.f, c = 0.f;
    const float4* xgp = (const float4*)(xg + (size_t)b * TSEQ * 64) + u;
    float4 buf[4];
#pragma unroll
    for (int i = 0; i < 4; i++) buf[i] = xgp[(size_t)i * 16];
    for (int ts = 0; ts < TSEQ; ts += 4) {
#pragma unroll
        for (int j = 0; j < 4; j++) {
            float4 a = buf[j];
            int nts = ts + j + 4;
            if (nts < TSEQ) buf[j] = xgp[(size_t)nts * 16];
            float gi = a.x, gf = a.y, gg = a.z, go = a.w;
#pragma unroll
            for (int k = 0; k < 16; k++) {
                float hk = __shfl_sync(0xffffffffu, h, k, 16);
                gi += wi[k] * hk; gf += wf[k] * hk; gg += wg[k] * hk; go += wo[k] * hk;
            }
            c = sigf(gf) * c + sigf(gi) * tanha(gg);
            h = sigf(go) * tanha(c);
            hout[((size_t)b * TSEQ + ts + j) * 16 + u] = h;
        }
    }
}

// ---------------- launch ----------------
extern "C" void kernel_launch(void* const* d_in, const int* in_sizes, int n_in,
                              void* d_out, int out_size) {
    const float* x      = (const float*)d_in[0];
    const float* conv_w = (const float*)d_in[1];
    const float* conv_b = (const float*)d_in[2];
    const float* Wih1   = (const float*)d_in[3];
    const float* Whh1   = (const float*)d_in[4];
    const float* bih1   = (const float*)d_in[5];
    const float* bhh1   = (const float*)d_in[6];
    const float* Wih2   = (const float*)d_in[7];
    const float* Whh2   = (const float*)d_in[8];
    const float* bih2   = (const float*)d_in[9];
    const float* bhh2   = (const float*)d_in[10];
    const float* Wih3   = (const float*)d_in[11];
    const float* Whh3   = (const float*)d_in[12];
    const float* bih3   = (const float*)d_in[13];
    const float* bhh3   = (const float*)d_in[14];
    float* out = (float*)d_out;

    __nv_bfloat16 *p_ch, *p_cl, *p_wch, *p_wcl, *p_w1h, *p_w1l;
    float *p_xg1, *p_h1, *p_xg2, *p_h2, *p_xg3;
    float *p_w1p, *p_b1p, *p_w2p, *p_b2p, *p_w3p, *p_b3p;
    cudaGetSymbolAddress((void**)&p_ch,  g_ch);
    cudaGetSymbolAddress((void**)&p_cl,  g_cl);
    cudaGetSymbolAddress((void**)&p_wch, g_wch);
    cudaGetSymbolAddress((void**)&p_wcl, g_wcl);
    cudaGetSymbolAddress((void**)&p_w1h, g_w1h);
    cudaGetSymbolAddress((void**)&p_w1l, g_w1l);
    cudaGetSymbolAddress((void**)&p_xg1, g_xg1);
    cudaGetSymbolAddress((void**)&p_h1,  g_h1);
    cudaGetSymbolAddress((void**)&p_xg2, g_xg2);
    cudaGetSymbolAddress((void**)&p_h2,  g_h2);
    cudaGetSymbolAddress((void**)&p_xg3, g_xg3);
    cudaGetSymbolAddress((void**)&p_w1p, g_w1p);
    cudaGetSymbolAddress((void**)&p_b1p, g_b1p);
    cudaGetSymbolAddress((void**)&p_w2p, g_w2p);
    cudaGetSymbolAddress((void**)&p_b2p, g_b2p);
    cudaGetSymbolAddress((void**)&p_w3p, g_w3p);
    cudaGetSymbolAddress((void**)&p_b3p, g_b3p);

    cudaFuncSetAttribute(k_convh, cudaFuncAttributeMaxDynamicSharedMemorySize, CSMEM);
    cudaFuncSetAttribute(k_g1h,   cudaFuncAttributeMaxDynamicSharedMemorySize, G_SMEM);

    // prep (tiny)
    k_perm<<<64, 256>>>(Wih1, bih1, bhh1, p_w1p, p_b1p, 32, 128);
    k_perm<<<8,  256>>>(Wih2, bih2, bhh2, p_w2p, p_b2p, 16, 32);
    k_perm<<<8,  256>>>(Wih3, bih3, bhh3, p_w3p, p_b3p, 32, 16);
    k_wconvsplit<<<320, 256>>>(conv_w, p_wch, p_wcl);
    k_w1split<<<64, 256>>>(p_w1p, p_w1h, p_w1l);

    // conv (HMMA, 3-term bf16 split) -> bf16 hi/lo conv output
    {
        dim3 g(8, BATCH);
        k_convh<<<g, 256, CSMEM>>>(x, p_wch, p_wcl, conv_b, p_ch, p_cl);
    }
    // layer 1: xg1 (HMMA) ; scan H=32
    k_g1h<<<MROWS / 128, 256, G_SMEM>>>(p_ch, p_cl, p_w1h, p_w1l, p_b1p, p_xg1);
    k_scan32<<<BATCH, 32>>>(p_xg1, Whh1, p_h1, nullptr);
    // layer 2
    k_gemm<64, 32><<<MROWS / 64, 256>>>(p_h1, p_w2p, p_b2p, p_xg2);
    k_scan16<<<BATCH / 2, 32>>>(p_xg2, Whh2, p_h2);
    // layer 3
    k_gemm<128, 16><<<MROWS / 64, 256>>>(p_h2, p_w3p, p_b3p, p_xg3);
    k_scan32<<<BATCH, 32>>>(p_xg3, Whh3, nullptr, out);
}

// round 11
// speedup vs baseline: 2.5754x; 1.4961x over previous
#include <cuda_runtime.h>
#include <cuda_bf16.h>
#include <cuda_fp16.h>
#include <cstdint>

#define BATCH 512
#define TSEQ  1020
#define MROWS (BATCH * TSEQ)   // 522240

// ---------------- device scratch (no runtime allocation) ----------------
__device__ __align__(256) __half g_ch [66846720]; // conv out hi (fp16), [b][oc][l] flat
__device__ __align__(256) __half g_cl [66846720]; // conv out lo (fp16)
__device__ __align__(256) float g_xg1 [66846720];  // [M][128] gate-permuted
__device__ __align__(256) float g_h1  [16711680];  // [M][32]
__device__ __align__(256) float g_xg2 [33423360];  // [M][64]
__device__ __align__(256) float g_h2  [ 8355840];  // [M][16]
__device__ __align__(256) float g_xg3 [66846720];  // [M][128]
__device__ __align__(256) float g_w1p [16384];
__device__ __align__(256) float g_b1p [128];
__device__ __align__(256) float g_w2p [2048];
__device__ __align__(256) float g_b2p [64];
__device__ __align__(256) float g_w3p [2048];
__device__ __align__(256) float g_b3p [128];
__device__ __align__(256) __half g_wc [81920];    // conv W fp16 [tap][oc][ic]
__device__ __align__(256) __half g_w1h[16384];    // Wih1 perm fp16 [gate][k]

__device__ __forceinline__ float sigf(float x){ return __fdividef(1.0f, 1.0f + __expf(-x)); }
__device__ __forceinline__ float tanha(float x){ return 2.0f*__fdividef(1.0f,1.0f+__expf(-2.0f*x)) - 1.0f; }
__device__ __forceinline__ void splith(float v, __half& h, __half& l){
    h = __float2half(v);
    l = __float2half(v - __half2float(h));
}
__device__ __forceinline__ uint32_t packh(__half a, __half b){
    return (uint32_t)__half_as_ushort(a) | ((uint32_t)__half_as_ushort(b) << 16);
}

// m16n8k16 fp16 MMA, f32 accum (sm_80+, target-portable)
#define MMAF16(c, a, b) \
    asm volatile("mma.sync.aligned.m16n8k16.row.col.f32.f16.f16.f32 " \
                 "{%0,%1,%2,%3},{%4,%5,%6,%7},{%8,%9},{%0,%1,%2,%3};" \
                 : "+f"((c)[0]), "+f"((c)[1]), "+f"((c)[2]), "+f"((c)[3]) \
                 : "r"((a)[0]), "r"((a)[1]), "r"((a)[2]), "r"((a)[3]), \
                   "r"((b)[0]), "r"((b)[1]))

// ---------------- small prep kernels ----------------
__global__ void k_perm(const float* __restrict__ Wih, const float* __restrict__ bih,
                       const float* __restrict__ bhh, float* __restrict__ Wp,
                       float* __restrict__ bp, int H, int K) {
    int idx = blockIdx.x * 256 + threadIdx.x;
    int N = 4 * H;
    if (idx < N * K) {
        int p = idx / K, k = idx % K;
        int j = p & 3, l = p >> 2;
        Wp[idx] = Wih[(j * H + l) * K + k];
    }
    if (idx < N) {
        int j = idx & 3, l = idx >> 2;
        bp[idx] = bih[j * H + l] + bhh[j * H + l];
    }
}
__global__ void k_wconvh(const float* __restrict__ w, __half* __restrict__ wc) {
    int idx = blockIdx.x * 256 + threadIdx.x;
    if (idx >= 81920) return;
    int k = idx / 16384, rem = idx % 16384, oc = rem / 128, ic = rem % 128;
    wc[idx] = __float2half(w[oc * 640 + ic * 5 + k]);
}
__global__ void k_w1half(const float* __restrict__ w, __half* __restrict__ wh) {
    int idx = blockIdx.x * 256 + threadIdx.x;
    if (idx >= 16384) return;
    wh[idx] = __float2half(w[idx]);
}

// ---------------- HMMA conv: C[oc][l] = sum_{tap} W_tap @ X(shift tap) ----------------
// A = W_tap single fp16 (staged per tap); B = x split fp16 hi/lo (built once).
// grid (8 l-tiles of 128, 512 batches), 256 threads (8 warps of 64oc x 32l).
#define CXS   0
#define CXTH  68096
#define CXTL  104000
#define CASH  139904
#define CSMEM 174720
__global__ __launch_bounds__(256) void k_convh(const float* __restrict__ x,
        const __half* __restrict__ wc, const float* __restrict__ cb,
        __half* __restrict__ ch, __half* __restrict__ cl) {
    extern __shared__ char sm[];
    float* xs = (float*)(sm + CXS);
    const int t = threadIdx.x, warp = t >> 5, lane = t & 31;
    const int g = lane >> 2, tid4 = lane & 3;
    const int wm = warp >> 2;      // 0..1 : oc group of 64
    const int wn = warp & 3;       // 0..3 : l group of 32
    const int l0 = blockIdx.x * 128, b = blockIdx.y;

    // stage x tile fp32 [128 ic][132 cols]
    for (int i = t; i < 128 * 132; i += 256) {
        int ic = i / 132, col = i - ic * 132;
        int gc = l0 + col;
        xs[ic * 133 + col] = (gc < 1024) ? x[(size_t)b * 131072 + ic * 1024 + gc] : 0.f;
    }
    __syncthreads();
    // build split transpose XT[l][ic] fp16 hi/lo (pitch 272B); taps = row offsets
    for (int i = t; i < 132 * 64; i += 256) {
        int l = i >> 6, icp = i & 63;
        float v0 = xs[(2 * icp) * 133 + l];
        float v1 = xs[(2 * icp + 1) * 133 + l];
        __half h0, q0, h1, q1;
        splith(v0, h0, q0); splith(v1, h1, q1);
        *(uint32_t*)(sm + CXTH + l * 272 + icp * 4) = packh(h0, h1);
        *(uint32_t*)(sm + CXTL + l * 272 + icp * 4) = packh(q0, q1);
    }
    __syncthreads();

    float c[4][4][4];
#pragma unroll
    for (int mt = 0; mt < 4; mt++)
#pragma unroll
        for (int nt = 0; nt < 4; nt++)
#pragma unroll
            for (int j = 0; j < 4; j++) c[mt][nt][j] = 0.f;

#pragma unroll 1
    for (int tap = 0; tap < 5; tap++) {
        // stage W_tap fp16 [128 oc][128 ic] -> pitch-272 smem
        for (int i = t; i < 2048; i += 256) {
            int row = i >> 4, q = i & 15;
            *(uint4*)(sm + CASH + row * 272 + q * 16) =
                *(const uint4*)(wc + tap * 16384 + row * 128 + q * 8);
        }
        __syncthreads();
#pragma unroll
        for (int kc = 0; kc < 8; kc++) {
            uint32_t a[4][4], bh[4][2], bl[4][2];
            const int kb = kc * 32 + tid4 * 4;
#pragma unroll
            for (int mt = 0; mt < 4; mt++) {
                const char* p = sm + CASH + (wm * 64 + mt * 16 + g) * 272 + kb;
                a[mt][0] = *(const uint32_t*)(p);
                a[mt][1] = *(const uint32_t*)(p + 8 * 272);
                a[mt][2] = *(const uint32_t*)(p + 16);
                a[mt][3] = *(const uint32_t*)(p + 8 * 272 + 16);
            }
#pragma unroll
            for (int nt = 0; nt < 4; nt++) {
                const int roff = (wn * 32 + nt * 8 + g + tap) * 272 + kb;
                bh[nt][0] = *(const uint32_t*)(sm + CXTH + roff);
                bh[nt][1] = *(const uint32_t*)(sm + CXTH + roff + 16);
                bl[nt][0] = *(const uint32_t*)(sm + CXTL + roff);
                bl[nt][1] = *(const uint32_t*)(sm + CXTL + roff + 16);
            }
#pragma unroll
            for (int mt = 0; mt < 4; mt++)
#pragma unroll
                for (int nt = 0; nt < 4; nt++) {
                    MMAF16(c[mt][nt], a[mt], bh[nt]);
                    MMAF16(c[mt][nt], a[mt], bl[nt]);
                }
        }
        __syncthreads();
    }

    // epilogue: +bias, split to fp16 hi/lo, store [b][oc][l]
#pragma unroll
    for (int mt = 0; mt < 4; mt++) {
        int oc = wm * 64 + mt * 16 + g;
        float b0 = __ldg(&cb[oc]), b8 = __ldg(&cb[oc + 8]);
        size_t r0 = ((size_t)b * 128 + oc) * 1020;
        size_t r8 = r0 + 8 * 1020;
#pragma unroll
        for (int nt = 0; nt < 4; nt++) {
            int lg = l0 + wn * 32 + nt * 8 + 2 * tid4;
            if (lg < 1020) {
                float v0 = c[mt][nt][0] + b0, v1 = c[mt][nt][1] + b0;
                float v2 = c[mt][nt][2] + b8, v3 = c[mt][nt][3] + b8;
                __half h0, q0, h1, q1, h2, q2, h3, q3;
                splith(v0, h0, q0); splith(v1, h1, q1);
                splith(v2, h2, q2); splith(v3, h3, q3);
                *(uint32_t*)&ch[r0 + lg] = packh(h0, h1);
                *(uint32_t*)&cl[r0 + lg] = packh(q0, q1);
                *(uint32_t*)&ch[r8 + lg] = packh(h2, h3);
                *(uint32_t*)&cl[r8 + lg] = packh(q2, q3);
            }
        }
    }
}

// ---------------- HMMA GEMM1: xg1[m][gate] = A[m][:]·W1p[gate][:] + b ----------------
// A = conv out fp16 hi/lo pair; B = W1 single fp16.
#define G_BI  0
#define G_ASH 512
#define G_ASL 35328
#define G_BS  70144
#define G_SMEM 104960
__global__ __launch_bounds__(256) void k_g1h(const __half* __restrict__ ah,
        const __half* __restrict__ al, const __half* __restrict__ w1h,
        const float* __restrict__ bp, float* __restrict__ xg) {
    extern __shared__ char sm[];
    float* bs = (float*)(sm + G_BI);
    const int t = threadIdx.x, warp = t >> 5, lane = t & 31;
    const int g = lane >> 2, tid4 = lane & 3;
    const int wm = warp >> 2;
    const int wn = warp & 3;
    const size_t m0 = (size_t)blockIdx.x * 128;

    if (t < 128) bs[t] = bp[t];
    for (int i = t; i < 2048; i += 256) {
        int row = i >> 4, q = i & 15;
        *(uint4*)(sm + G_ASH + row * 272 + q * 16) = *(const uint4*)(ah + (m0 + row) * 128 + q * 8);
        *(uint4*)(sm + G_ASL + row * 272 + q * 16) = *(const uint4*)(al + (m0 + row) * 128 + q * 8);
        *(uint4*)(sm + G_BS  + row * 272 + q * 16) = *(const uint4*)(w1h + row * 128 + q * 8);
    }
    __syncthreads();

    float c[4][4][4];
#pragma unroll
    for (int mt = 0; mt < 4; mt++)
#pragma unroll
        for (int nt = 0; nt < 4; nt++)
#pragma unroll
            for (int j = 0; j < 4; j++) c[mt][nt][j] = 0.f;

#pragma unroll
    for (int kc = 0; kc < 8; kc++) {
        uint32_t a[4][4], al_[4][4], bf[4][2];
        const int kb = kc * 32 + tid4 * 4;
#pragma unroll
        for (int mt = 0; mt < 4; mt++) {
            const int roff = (wm * 64 + mt * 16 + g) * 272 + kb;
            a[mt][0]  = *(const uint32_t*)(sm + G_ASH + roff);
            a[mt][1]  = *(const uint32_t*)(sm + G_ASH + roff + 8 * 272);
            a[mt][2]  = *(const uint32_t*)(sm + G_ASH + roff + 16);
            a[mt][3]  = *(const uint32_t*)(sm + G_ASH + roff + 8 * 272 + 16);
            al_[mt][0] = *(const uint32_t*)(sm + G_ASL + roff);
            al_[mt][1] = *(const uint32_t*)(sm + G_ASL + roff + 8 * 272);
            al_[mt][2] = *(const uint32_t*)(sm + G_ASL + roff + 16);
            al_[mt][3] = *(const uint32_t*)(sm + G_ASL + roff + 8 * 272 + 16);
        }
#pragma unroll
        for (int nt = 0; nt < 4; nt++) {
            const char* p = sm + G_BS + (wn * 32 + nt * 8 + g) * 272 + kb;
            bf[nt][0] = *(const uint32_t*)(p);
            bf[nt][1] = *(const uint32_t*)(p + 16);
        }
#pragma unroll
        for (int mt = 0; mt < 4; mt++)
#pragma unroll
            for (int nt = 0; nt < 4; nt++) {
                MMAF16(c[mt][nt], a[mt], bf[nt]);
                MMAF16(c[mt][nt], al_[mt], bf[nt]);
            }
    }

#pragma unroll
    for (int mt = 0; mt < 4; mt++) {
        size_t m = m0 + wm * 64 + mt * 16 + g;
#pragma unroll
        for (int nt = 0; nt < 4; nt++) {
            int col = wn * 32 + nt * 8 + 2 * tid4;
            float bx = bs[col], by = bs[col + 1];
            float2 o0 = { c[mt][nt][0] + bx, c[mt][nt][1] + by };
            float2 o1 = { c[mt][nt][2] + bx, c[mt][nt][3] + by };
            *(float2*)&xg[m * 128 + col] = o0;
            *(float2*)&xg[(m + 8) * 128 + col] = o1;
        }
    }
}

// ---------------- fp32 GEMM for layers 2/3 ----------------
template <int N, int K>
__global__ __launch_bounds__(256) void k_gemm(const float* __restrict__ A,
                                              const float* __restrict__ Wp,
                                              const float* __restrict__ bp,
                                              float* __restrict__ Xg) {
    constexpr int KC = 16;
    constexpr int CG = N / 4;
    constexpr int RG = 256 / CG;
    constexpr int RPT = 64 / RG;
    __shared__ float As[64][KC];
    __shared__ float Ws[KC][N];
    const int t = threadIdx.x;
    const int cg = t % CG, rg = t / CG;
    const size_t m0 = (size_t)blockIdx.x * 64;
    float acc[RPT][4];
#pragma unroll
    for (int r = 0; r < RPT; r++)
#pragma unroll
        for (int j = 0; j < 4; j++) acc[r][j] = 0.f;
    for (int kc = 0; kc < K; kc += KC) {
        {
            int row = t >> 2, k4 = (t & 3) * 4;
            *(float4*)&As[row][k4] = *(const float4*)&A[(m0 + row) * K + kc + k4];
        }
#pragma unroll
        for (int e = 0; e < N * KC / 256; e++) {
            int idx = t + e * 256;
            int p = idx % N, kk = idx / N;
            Ws[kk][p] = Wp[p * K + kc + kk];
        }
        __syncthreads();
#pragma unroll
        for (int kk = 0; kk < KC; kk++) {
            float4 w4 = *(const float4*)&Ws[kk][cg * 4];
#pragma unroll
            for (int r = 0; r < RPT; r++) {
                float av = As[rg * RPT + r][kk];
                acc[r][0] += av * w4.x; acc[r][1] += av * w4.y;
                acc[r][2] += av * w4.z; acc[r][3] += av * w4.w;
            }
        }
        __syncthreads();
    }
    float4 bv = *(const float4*)&bp[cg * 4];
#pragma unroll
    for (int r = 0; r < RPT; r++) {
        size_t m = m0 + rg * RPT + r;
        float4 o = { acc[r][0] + bv.x, acc[r][1] + bv.y, acc[r][2] + bv.z, acc[r][3] + bv.w };
        *(float4*)&Xg[m * N + cg * 4] = o;
    }
}

// ---------------- LSTM scans (prefetch + 4-way split accumulators) ----------------
__global__ __launch_bounds__(32) void k_scan32(const float* __restrict__ xg,
                                               const float* __restrict__ whh,
                                               float* __restrict__ hout,
                                               float* __restrict__ lastout) {
    const int b = blockIdx.x, l = threadIdx.x;
    float wi[32], wf[32], wg[32], wo[32];
#pragma unroll
    for (int k = 0; k < 32; k++) {
        wi[k] = whh[(0 * 32 + l) * 32 + k];
        wf[k] = whh[(1 * 32 + l) * 32 + k];
        wg[k] = whh[(2 * 32 + l) * 32 + k];
        wo[k] = whh[(3 * 32 + l) * 32 + k];
    }
    float h = 0.f, c = 0.f;
    const float4* xgp = (const float4*)(xg + (size_t)b * TSEQ * 128) + l;
    float4 buf[4];
#pragma unroll
    for (int i = 0; i < 4; i++) buf[i] = xgp[(size_t)i * 32];
    for (int ts = 0; ts < TSEQ; ts += 4) {
#pragma unroll
        for (int j = 0; j < 4; j++) {
            float4 a = buf[j];
            int nts = ts + j + 4;
            if (nts < TSEQ) buf[j] = xgp[(size_t)nts * 32];
            float gi[4] = {a.x, 0.f, 0.f, 0.f};
            float gf[4] = {a.y, 0.f, 0.f, 0.f};
            float gg[4] = {a.z, 0.f, 0.f, 0.f};
            float go[4] = {a.w, 0.f, 0.f, 0.f};
#pragma unroll
            for (int q = 0; q < 4; q++)
#pragma unroll
                for (int k = 0; k < 8; k++) {
                    float hk = __shfl_sync(0xffffffffu, h, q * 8 + k);
                    gi[q] += wi[q * 8 + k] * hk;
                    gf[q] += wf[q * 8 + k] * hk;
                    gg[q] += wg[q * 8 + k] * hk;
                    go[q] += wo[q * 8 + k] * hk;
                }
            float gI = (gi[0] + gi[1]) + (gi[2] + gi[3]);
            float gF = (gf[0] + gf[1]) + (gf[2] + gf[3]);
            float gG = (gg[0] + gg[1]) + (gg[2] + gg[3]);
            float gO = (go[0] + go[1]) + (go[2] + go[3]);
            c = sigf(gF) * c + sigf(gI) * tanha(gG);
            h = sigf(gO) * tanha(c);
            if (hout) hout[((size_t)b * TSEQ + ts + j) * 32 + l] = h;
        }
    }
    if (lastout) lastout[b * 32 + l] = h;
}
__global__ __launch_bounds__(32) void k_scan16(const float* __restrict__ xg,
                                               const float* __restrict__ whh,
                                               float* __restrict__ hout) {
    const int lane = threadIdx.x;
    const int u = lane & 15;
    const int b = blockIdx.x * 2 + (lane >> 4);
    float wi[16], wf[16], wg[16], wo[16];
#pragma unroll
    for (int k = 0; k < 16; k++) {
        wi[k] = whh[(0 * 16 + u) * 16 + k];
        wf[k] = whh[(1 * 16 + u) * 16 + k];
        wg[k] = whh[(2 * 16 + u) * 16 + k];
        wo[k] = whh[(3 * 16 + u) * 16 + k];
    }
    float h = 0.f, c = 0.f;
    const float4* xgp = (const float4*)(xg + (size_t)b * TSEQ * 64) + u;
    float4 buf[4];
#pragma unroll
    for (int i = 0; i < 4; i++) buf[i] = xgp[(size_t)i * 16];
    for (int ts = 0; ts < TSEQ; ts += 4) {
#pragma unroll
        for (int j = 0; j < 4; j++) {
            float4 a = buf[j];
            int nts = ts + j + 4;
            if (nts < TSEQ) buf[j] = xgp[(size_t)nts * 16];
            float gi[2] = {a.x, 0.f}, gf[2] = {a.y, 0.f};
            float gg[2] = {a.z, 0.f}, go[2] = {a.w, 0.f};
#pragma unroll
            for (int q = 0; q < 2; q++)
#pragma unroll
                for (int k = 0; k < 8; k++) {
                    float hk = __shfl_sync(0xffffffffu, h, q * 8 + k, 16);
                    gi[q] += wi[q * 8 + k] * hk;
                    gf[q] += wf[q * 8 + k] * hk;
                    gg[q] += wg[q * 8 + k] * hk;
                    go[q] += wo[q * 8 + k] * hk;
                }
            c = sigf(gf[0] + gf[1]) * c + sigf(gi[0] + gi[1]) * tanha(gg[0] + gg[1]);
            h = sigf(go[0] + go[1]) * tanha(c);
            hout[((size_t)b * TSEQ + ts + j) * 16 + u] = h;
        }
    }
}

// ---------------- launch ----------------
extern "C" void kernel_launch(void* const* d_in, const int* in_sizes, int n_in,
                              void* d_out, int out_size) {
    const float* x      = (const float*)d_in[0];
    const float* conv_w = (const float*)d_in[1];
    const float* conv_b = (const float*)d_in[2];
    const float* Wih1   = (const float*)d_in[3];
    const float* Whh1   = (const float*)d_in[4];
    const float* bih1   = (const float*)d_in[5];
    const float* bhh1   = (const float*)d_in[6];
    const float* Wih2   = (const float*)d_in[7];
    const float* Whh2   = (const float*)d_in[8];
    const float* bih2   = (const float*)d_in[9];
    const float* bhh2   = (const float*)d_in[10];
    const float* Wih3   = (const float*)d_in[11];
    const float* Whh3   = (const float*)d_in[12];
    const float* bih3   = (const float*)d_in[13];
    const float* bhh3   = (const float*)d_in[14];
    float* out = (float*)d_out;

    __half *p_ch, *p_cl, *p_wc, *p_w1h;
    float *p_xg1, *p_h1, *p_xg2, *p_h2, *p_xg3;
    float *p_w1p, *p_b1p, *p_w2p, *p_b2p, *p_w3p, *p_b3p;
    cudaGetSymbolAddress((void**)&p_ch,  g_ch);
    cudaGetSymbolAddress((void**)&p_cl,  g_cl);
    cudaGetSymbolAddress((void**)&p_wc,  g_wc);
    cudaGetSymbolAddress((void**)&p_w1h, g_w1h);
    cudaGetSymbolAddress((void**)&p_xg1, g_xg1);
    cudaGetSymbolAddress((void**)&p_h1,  g_h1);
    cudaGetSymbolAddress((void**)&p_xg2, g_xg2);
    cudaGetSymbolAddress((void**)&p_h2,  g_h2);
    cudaGetSymbolAddress((void**)&p_xg3, g_xg3);
    cudaGetSymbolAddress((void**)&p_w1p, g_w1p);
    cudaGetSymbolAddress((void**)&p_b1p, g_b1p);
    cudaGetSymbolAddress((void**)&p_w2p, g_w2p);
    cudaGetSymbolAddress((void**)&p_b2p, g_b2p);
    cudaGetSymbolAddress((void**)&p_w3p, g_w3p);
    cudaGetSymbolAddress((void**)&p_b3p, g_b3p);

    cudaFuncSetAttribute(k_convh, cudaFuncAttributeMaxDynamicSharedMemorySize, CSMEM);
    cudaFuncSetAttribute(k_g1h,   cudaFuncAttributeMaxDynamicSharedMemorySize, G_SMEM);

    // launch order chosen so k_convh is the 4th launch (ncu profiles it)
    k_wconvh<<<320, 256>>>(conv_w, p_wc);                                  // 1
    k_perm<<<64, 256>>>(Wih1, bih1, bhh1, p_w1p, p_b1p, 32, 128);          // 2
    k_w1half<<<64, 256>>>(p_w1p, p_w1h);                                   // 3
    {
        dim3 g(8, BATCH);
        k_convh<<<g, 256, CSMEM>>>(x, p_wc, conv_b, p_ch, p_cl);           // 4 <- profiled
    }
    k_perm<<<8,  256>>>(Wih2, bih2, bhh2, p_w2p, p_b2p, 16, 32);           // 5
    k_perm<<<8,  256>>>(Wih3, bih3, bhh3, p_w3p, p_b3p, 32, 16);           // 6
    // layer 1: xg1 (HMMA, fp16 2-term) ; scan H=32
    k_g1h<<<MROWS / 128, 256, G_SMEM>>>(p_ch, p_cl, p_w1h, p_b1p, p_xg1);
    k_scan32<<<BATCH, 32>>>(p_xg1, Whh1, p_h1, nullptr);
    // layer 2
    k_gemm<64, 32><<<MROWS / 64, 256>>>(p_h1, p_w2p, p_b2p, p_xg2);
    k_scan16<<<BATCH / 2, 32>>>(p_xg2, Whh2, p_h2);
    // layer 3
    k_gemm<128, 16><<<MROWS / 64, 256>>>(p_h2, p_w3p, p_b3p, p_xg3);
    k_scan32<<<BATCH, 32>>>(p_xg3, Whh3, nullptr, out);
}